// round 4
// baseline (speedup 1.0000x reference)
#include <cuda_runtime.h>
#include <cstdint>

#define N_NODES 50000
#define D 128
#define N_EDGES 625000

// Scratch (no cudaMalloc allowed)
__device__ float g_mean[(size_t)N_NODES * D];   // 25.6 MB
__device__ int   g_cnt[N_NODES];                // degree
__device__ int   g_start[N_NODES];              // CSR row start
__device__ int   g_pos[N_NODES];                // fill cursor
__device__ int   g_esrc[N_EDGES];               // dst-sorted src indices

// ---------------------------------------------------------------------------
// 0) zero the degree histogram
// ---------------------------------------------------------------------------
__global__ void zero_cnt_kernel() {
    int i = blockIdx.x * blockDim.x + threadIdx.x;
    if (i < N_NODES) g_cnt[i] = 0;
}

// ---------------------------------------------------------------------------
// 1) histogram of dst (degree)
// ---------------------------------------------------------------------------
__global__ void hist_kernel(const int* __restrict__ dst) {
    int i = blockIdx.x * blockDim.x + threadIdx.x;
    if (i < N_EDGES) atomicAdd(&g_cnt[dst[i]], 1);
}

// ---------------------------------------------------------------------------
// 2) single-block exclusive scan of g_cnt -> g_start, g_pos
// ---------------------------------------------------------------------------
#define SCAN_T 1024
#define SCAN_C 49   // ceil(50000/1024)

__global__ void __launch_bounds__(SCAN_T) scan_kernel() {
    __shared__ int part[SCAN_T];
    const int t = threadIdx.x;
    const int base = t * SCAN_C;

    int s = 0;
    #pragma unroll 7
    for (int i = 0; i < SCAN_C; i++) {
        int idx = base + i;
        if (idx < N_NODES) s += g_cnt[idx];
    }
    part[t] = s;
    __syncthreads();

    #pragma unroll
    for (int off = 1; off < SCAN_T; off <<= 1) {
        int v = (t >= off) ? part[t - off] : 0;
        __syncthreads();
        part[t] += v;
        __syncthreads();
    }
    int run = part[t] - s;

    #pragma unroll 7
    for (int i = 0; i < SCAN_C; i++) {
        int idx = base + i;
        if (idx < N_NODES) {
            g_start[idx] = run;
            g_pos[idx]   = run;
            run += g_cnt[idx];
        }
    }
}

// ---------------------------------------------------------------------------
// 3) fill dst-sorted edge list
// ---------------------------------------------------------------------------
__global__ void fill_kernel(const int* __restrict__ src,
                            const int* __restrict__ dst) {
    int i = blockIdx.x * blockDim.x + threadIdx.x;
    if (i < N_EDGES) {
        int slot = atomicAdd(&g_pos[dst[i]], 1);
        g_esrc[slot] = src[i];
    }
}

// ---------------------------------------------------------------------------
// 4) pull-aggregate: one warp per node, lane = one float4 column, MLP=4.
// ---------------------------------------------------------------------------
__global__ void __launch_bounds__(256) gather_kernel(const float4* __restrict__ x4)
{
    int node = (blockIdx.x * blockDim.x + threadIdx.x) >> 5;
    int lane = threadIdx.x & 31;
    if (node >= N_NODES) return;

    int start = g_start[node];
    int deg   = g_cnt[node];
    int end   = start + deg;

    float4 acc = make_float4(0.f, 0.f, 0.f, 0.f);
    int e = start;
    for (; e + 4 <= end; e += 4) {
        int i0 = __ldg(&g_esrc[e]);
        int i1 = __ldg(&g_esrc[e + 1]);
        int i2 = __ldg(&g_esrc[e + 2]);
        int i3 = __ldg(&g_esrc[e + 3]);
        float4 v0 = x4[(size_t)i0 * (D / 4) + lane];
        float4 v1 = x4[(size_t)i1 * (D / 4) + lane];
        float4 v2 = x4[(size_t)i2 * (D / 4) + lane];
        float4 v3 = x4[(size_t)i3 * (D / 4) + lane];
        acc.x += (v0.x + v1.x) + (v2.x + v3.x);
        acc.y += (v0.y + v1.y) + (v2.y + v3.y);
        acc.z += (v0.z + v1.z) + (v2.z + v3.z);
        acc.w += (v0.w + v1.w) + (v2.w + v3.w);
    }
    for (; e < end; e++) {
        int i0 = __ldg(&g_esrc[e]);
        float4 v0 = x4[(size_t)i0 * (D / 4) + lane];
        acc.x += v0.x; acc.y += v0.y; acc.z += v0.z; acc.w += v0.w;
    }

    float rdeg = 1.0f / fmaxf((float)deg, 1.0f);
    acc.x *= rdeg; acc.y *= rdeg; acc.z *= rdeg; acc.w *= rdeg;
    reinterpret_cast<float4*>(g_mean)[(size_t)node * (D / 4) + lane] = acc;
}

// ---------------------------------------------------------------------------
// 5) fused GEMM + epilogue:  out = x + relu( g_mean @ W_l + x @ W_r + b )
//    Round-2 inner loop (measured good). B streamed per K-chunk (8 KB) so
//    smem is ~17 KB static -> multiple blocks/SM instead of 1.
// ---------------------------------------------------------------------------
#define BM 128
#define KC 16
#define KTOT 256

union F2U { float2 f; unsigned long long u; };

__device__ __forceinline__ unsigned long long splat2(float v) {
    unsigned long long r;
    asm("mov.b64 %0, {%1, %1};" : "=l"(r) : "f"(v));
    return r;
}
__device__ __forceinline__ void fma2(unsigned long long& acc,
                                     unsigned long long a,
                                     unsigned long long b) {
    asm("fma.rn.f32x2 %0, %1, %2, %0;" : "+l"(acc) : "l"(a), "l"(b));
}

__global__ void __launch_bounds__(256) gemm_kernel(
    const float* __restrict__ x,
    const float* __restrict__ Wl,
    const float* __restrict__ bias,
    const float* __restrict__ Wr,
    float* __restrict__ out)
{
    __shared__ float Bs[KC * 128];     // 8 KB: current B chunk [kk][n]
    __shared__ float As[KC * 128];     // 8 KB: current A chunk [kk][m]
    __shared__ float bs[128];

    const int tid = threadIdx.x;
    const int row0 = blockIdx.x * BM;

    if (tid < 128) bs[tid] = bias[tid];

    const int tx = tid & 15;
    const int ty = tid >> 4;
    const int tx8 = tx * 8;
    const int ty8 = ty * 8;

    unsigned long long acc[8][4];
    #pragma unroll
    for (int i = 0; i < 8; i++)
        #pragma unroll
        for (int j = 0; j < 4; j++)
            acc[i][j] = 0ull;

    const int am  = tid & 127;
    const int akq = tid >> 7;            // 0 or 1
    int ar = row0 + am;
    if (ar >= N_NODES) ar = N_NODES - 1;
    const float4* mean4row = reinterpret_cast<const float4*>(g_mean + (size_t)ar * D);
    const float4* x4row    = reinterpret_cast<const float4*>(x + (size_t)ar * D);
    const float4* wl4 = reinterpret_cast<const float4*>(Wl);
    const float4* wr4 = reinterpret_cast<const float4*>(Wr);

    #pragma unroll 1
    for (int kt = 0; kt < KTOT / KC; kt++) {       // 16 chunks of KC=16
        const int k0 = kt * KC;
        const bool is_mean = (k0 < 128);
        const float4* srow = is_mean ? mean4row : x4row;
        const float4* w4   = is_mean ? wl4 : wr4;
        const int krel = is_mean ? k0 : (k0 - 128);   // row in W (0..112)
        const int kb4  = krel >> 2;                   // float4 base in A row

        // Load B chunk: KC rows x 128 cols = 512 float4; 2 per thread.
        // float4 index f: row kk = f>>5, col4 = f&31.
        {
            int f0 = tid;          // 0..255
            int f1 = tid + 256;    // 256..511
            reinterpret_cast<float4*>(Bs)[f0] =
                w4[(size_t)(krel + (f0 >> 5)) * 32 + (f0 & 31)];
            reinterpret_cast<float4*>(Bs)[f1] =
                w4[(size_t)(krel + (f1 >> 5)) * 32 + (f1 & 31)];
        }

        // Load & transpose A chunk: 256 threads cover 128 m x 4 float4-cols
        #pragma unroll
        for (int i = 0; i < 2; i++) {
            int kk4 = akq * 2 + i;       // 0..3
            float4 v = srow[kb4 + kk4];
            int kk = kk4 * 4;
            As[(kk + 0) * 128 + am] = v.x;
            As[(kk + 1) * 128 + am] = v.y;
            As[(kk + 2) * 128 + am] = v.z;
            As[(kk + 3) * 128 + am] = v.w;
        }
        __syncthreads();

        #pragma unroll
        for (int kk = 0; kk < KC; kk++) {
            const float4 a0 = *reinterpret_cast<const float4*>(&As[kk * 128 + ty8]);
            const float4 a1 = *reinterpret_cast<const float4*>(&As[kk * 128 + ty8 + 4]);
            const float4 b0 = *reinterpret_cast<const float4*>(&Bs[kk * 128 + tx8]);
            const float4 b1 = *reinterpret_cast<const float4*>(&Bs[kk * 128 + tx8 + 4]);

            unsigned long long bp[4];
            { F2U u; u.f = make_float2(b0.x, b0.y); bp[0] = u.u; }
            { F2U u; u.f = make_float2(b0.z, b0.w); bp[1] = u.u; }
            { F2U u; u.f = make_float2(b1.x, b1.y); bp[2] = u.u; }
            { F2U u; u.f = make_float2(b1.z, b1.w); bp[3] = u.u; }

            float av[8] = {a0.x, a0.y, a0.z, a0.w, a1.x, a1.y, a1.z, a1.w};
            #pragma unroll
            for (int m = 0; m < 8; m++) {
                unsigned long long as_ = splat2(av[m]);
                #pragma unroll
                for (int j = 0; j < 4; j++)
                    fma2(acc[m][j], as_, bp[j]);
            }
        }
        __syncthreads();
    }

    const float4 ba = *reinterpret_cast<const float4*>(&bs[tx8]);
    const float4 bb = *reinterpret_cast<const float4*>(&bs[tx8 + 4]);
    #pragma unroll
    for (int m = 0; m < 8; m++) {
        int r = row0 + ty8 + m;
        if (r < N_NODES) {
            const float4* xr = reinterpret_cast<const float4*>(x + (size_t)r * D + tx8);
            float4* outr = reinterpret_cast<float4*>(out + (size_t)r * D + tx8);
            float4 xa = xr[0], xb = xr[1];
            F2U u; float4 o;
            u.u = acc[m][0];
            o.x = xa.x + fmaxf(u.f.x + ba.x, 0.f);
            o.y = xa.y + fmaxf(u.f.y + ba.y, 0.f);
            u.u = acc[m][1];
            o.z = xa.z + fmaxf(u.f.x + ba.z, 0.f);
            o.w = xa.w + fmaxf(u.f.y + ba.w, 0.f);
            outr[0] = o;
            u.u = acc[m][2];
            o.x = xb.x + fmaxf(u.f.x + bb.x, 0.f);
            o.y = xb.y + fmaxf(u.f.y + bb.y, 0.f);
            u.u = acc[m][3];
            o.z = xb.z + fmaxf(u.f.x + bb.z, 0.f);
            o.w = xb.w + fmaxf(u.f.y + bb.w, 0.f);
            outr[1] = o;
        }
    }
}

// ---------------------------------------------------------------------------
extern "C" void kernel_launch(void* const* d_in, const int* in_sizes, int n_in,
                              void* d_out, int out_size)
{
    const float* x  = (const float*)d_in[0];
    const int*   ei = (const int*)d_in[1];      // [2, E]: src = ei[0:E], dst = ei[E:2E]
    const float* Wl = (const float*)d_in[2];
    const float* bl = (const float*)d_in[3];
    const float* Wr = (const float*)d_in[4];
    float* out = (float*)d_out;

    const int* src = ei;
    const int* dst = ei + N_EDGES;

    zero_cnt_kernel<<<(N_NODES + 255) / 256, 256>>>();
    hist_kernel<<<(N_EDGES + 255) / 256, 256>>>(dst);
    scan_kernel<<<1, SCAN_T>>>();
    fill_kernel<<<(N_EDGES + 255) / 256, 256>>>(src, dst);

    {
        long long threads = (long long)N_NODES * 32;
        int blocks = (int)((threads + 255) / 256);
        gather_kernel<<<blocks, 256>>>(reinterpret_cast<const float4*>(x));
    }

    {
        int grid = (N_NODES + BM - 1) / BM;   // 391
        gemm_kernel<<<grid, 256>>>(x, Wl, bl, Wr, out);
    }
}

// round 5
// speedup vs baseline: 1.7501x; 1.7501x over previous
#include <cuda_runtime.h>
#include <cstdint>

#define N_NODES 50000
#define D 128
#define N_EDGES 625000
#define SCAN_BLK 256
#define N_SCAN_BLOCKS ((N_NODES + SCAN_BLK - 1) / SCAN_BLK)   // 196

// Scratch (no cudaMalloc allowed)
__device__ float g_mean[(size_t)N_NODES * D];   // 25.6 MB
__device__ int   g_cnt[N_NODES];                // degree (histogram)
__device__ int   g_start[N_NODES];              // CSR row start
__device__ int   g_pos[N_NODES];                // fill cursor
__device__ int   g_bsum[N_SCAN_BLOCKS];         // per-block scan sums
__device__ int   g_boff[N_SCAN_BLOCKS];         // scanned block offsets
__device__ int   g_esrc[N_EDGES];               // dst-sorted src indices

// ---------------------------------------------------------------------------
// 1) zero the degree histogram
// ---------------------------------------------------------------------------
__global__ void zero_cnt_kernel() {
    int i = blockIdx.x * blockDim.x + threadIdx.x;
    if (i < N_NODES) g_cnt[i] = 0;
}

// ---------------------------------------------------------------------------
// 2) histogram of dst (degree)
// ---------------------------------------------------------------------------
__global__ void hist_kernel(const int* __restrict__ dst) {
    int i = blockIdx.x * blockDim.x + threadIdx.x;
    if (i < N_EDGES) atomicAdd(&g_cnt[dst[i]], 1);
}

// ---------------------------------------------------------------------------
// 3a) per-block exclusive scan of g_cnt, block sums to g_bsum
// ---------------------------------------------------------------------------
__global__ void scan1_kernel() {
    __shared__ int sh[SCAN_BLK];
    int t = threadIdx.x;
    int i = blockIdx.x * SCAN_BLK + t;
    int v = (i < N_NODES) ? g_cnt[i] : 0;
    sh[t] = v;
    __syncthreads();
    #pragma unroll
    for (int off = 1; off < SCAN_BLK; off <<= 1) {
        int t2 = (t >= off) ? sh[t - off] : 0;
        __syncthreads();
        sh[t] += t2;
        __syncthreads();
    }
    if (i < N_NODES) g_start[i] = sh[t] - v;          // exclusive within block
    if (t == SCAN_BLK - 1) g_bsum[blockIdx.x] = sh[t];
}

// ---------------------------------------------------------------------------
// 3b) exclusive scan of the 196 block sums (single block)
// ---------------------------------------------------------------------------
__global__ void scan2_kernel() {
    __shared__ int sh[SCAN_BLK];
    int t = threadIdx.x;
    int v = (t < N_SCAN_BLOCKS) ? g_bsum[t] : 0;
    sh[t] = v;
    __syncthreads();
    #pragma unroll
    for (int off = 1; off < SCAN_BLK; off <<= 1) {
        int t2 = (t >= off) ? sh[t - off] : 0;
        __syncthreads();
        sh[t] += t2;
        __syncthreads();
    }
    if (t < N_SCAN_BLOCKS) g_boff[t] = sh[t] - v;
}

// ---------------------------------------------------------------------------
// 3c) add block offsets; init fill cursors
// ---------------------------------------------------------------------------
__global__ void scan3_kernel() {
    int i = blockIdx.x * blockDim.x + threadIdx.x;
    if (i < N_NODES) {
        int s = g_start[i] + g_boff[i >> 8];
        g_start[i] = s;
        g_pos[i] = s;
    }
}

// ---------------------------------------------------------------------------
// 4) fill dst-sorted edge list
// ---------------------------------------------------------------------------
__global__ void fill_kernel(const int* __restrict__ src,
                            const int* __restrict__ dst) {
    int i = blockIdx.x * blockDim.x + threadIdx.x;
    if (i < N_EDGES) {
        int slot = atomicAdd(&g_pos[dst[i]], 1);
        g_esrc[slot] = src[i];
    }
}

// ---------------------------------------------------------------------------
// 5) pull-aggregate: one warp per node, lane = one float4 column, MLP=4.
// ---------------------------------------------------------------------------
__global__ void __launch_bounds__(256) gather_kernel(const float4* __restrict__ x4)
{
    int node = (blockIdx.x * blockDim.x + threadIdx.x) >> 5;
    int lane = threadIdx.x & 31;
    if (node >= N_NODES) return;

    int start = g_start[node];
    int deg   = g_cnt[node];
    int end   = start + deg;

    float4 acc = make_float4(0.f, 0.f, 0.f, 0.f);
    int e = start;
    for (; e + 4 <= end; e += 4) {
        int i0 = __ldg(&g_esrc[e]);
        int i1 = __ldg(&g_esrc[e + 1]);
        int i2 = __ldg(&g_esrc[e + 2]);
        int i3 = __ldg(&g_esrc[e + 3]);
        float4 v0 = x4[(size_t)i0 * (D / 4) + lane];
        float4 v1 = x4[(size_t)i1 * (D / 4) + lane];
        float4 v2 = x4[(size_t)i2 * (D / 4) + lane];
        float4 v3 = x4[(size_t)i3 * (D / 4) + lane];
        acc.x += (v0.x + v1.x) + (v2.x + v3.x);
        acc.y += (v0.y + v1.y) + (v2.y + v3.y);
        acc.z += (v0.z + v1.z) + (v2.z + v3.z);
        acc.w += (v0.w + v1.w) + (v2.w + v3.w);
    }
    for (; e < end; e++) {
        int i0 = __ldg(&g_esrc[e]);
        float4 v0 = x4[(size_t)i0 * (D / 4) + lane];
        acc.x += v0.x; acc.y += v0.y; acc.z += v0.z; acc.w += v0.w;
    }

    float rdeg = 1.0f / fmaxf((float)deg, 1.0f);
    acc.x *= rdeg; acc.y *= rdeg; acc.z *= rdeg; acc.w *= rdeg;
    reinterpret_cast<float4*>(g_mean)[(size_t)node * (D / 4) + lane] = acc;
}

// ---------------------------------------------------------------------------
// 6) fused GEMM + epilogue:  out = x + relu( g_mean @ W_l + x @ W_r + b )
//    Round-2 core loop (measured good): full B cached in smem, KC=16,
//    LDS.128 B loads + repack. NEW: double-buffered A chunks so the per-chunk
//    A LDG is hidden under compute; one __syncthreads per chunk.
// ---------------------------------------------------------------------------
#define BM 128
#define KC 16
#define KTOT 256

union F2U { float2 f; unsigned long long u; };

__device__ __forceinline__ unsigned long long splat2(float v) {
    unsigned long long r;
    asm("mov.b64 %0, {%1, %1};" : "=l"(r) : "f"(v));
    return r;
}
__device__ __forceinline__ void fma2(unsigned long long& acc,
                                     unsigned long long a,
                                     unsigned long long b) {
    asm("fma.rn.f32x2 %0, %1, %2, %0;" : "+l"(acc) : "l"(a), "l"(b));
}

__global__ void __launch_bounds__(256, 1) gemm_kernel(
    const float* __restrict__ x,
    const float* __restrict__ Wl,
    const float* __restrict__ bias,
    const float* __restrict__ Wr,
    float* __restrict__ out)
{
    extern __shared__ float smem[];
    float* Bs = smem;                       // KTOT*128 floats (128 KB)
    float* As = smem + KTOT * 128;          // 2 * KC*128 floats (16 KB), [buf][k][m]
    float* bs = As + 2 * KC * 128;          // 128 floats

    const int tid = threadIdx.x;
    const int row0 = blockIdx.x * BM;

    // Stacked weights [W_l ; W_r] into Bs[k][n]
    {
        const float4* wl4 = reinterpret_cast<const float4*>(Wl);
        const float4* wr4 = reinterpret_cast<const float4*>(Wr);
        float4* Bs4 = reinterpret_cast<float4*>(Bs);
        #pragma unroll
        for (int i = 0; i < 16; i++)
            Bs4[tid + 256 * i] = wl4[tid + 256 * i];
        #pragma unroll
        for (int i = 0; i < 16; i++)
            Bs4[4096 + tid + 256 * i] = wr4[tid + 256 * i];
        if (tid < 128) bs[tid] = bias[tid];
    }

    const int tx = tid & 15;
    const int ty = tid >> 4;
    const int tx8 = tx * 8;
    const int ty8 = ty * 8;

    unsigned long long acc[8][4];
    #pragma unroll
    for (int i = 0; i < 8; i++)
        #pragma unroll
        for (int j = 0; j < 4; j++)
            acc[i][j] = 0ull;

    // A-load assignment: 256 threads cover 128 m-rows x 4 float4-cols per chunk
    const int am  = tid & 127;
    const int akq = tid >> 7;            // 0 or 1
    int ar = row0 + am;
    if (ar >= N_NODES) ar = N_NODES - 1;
    const float4* mean4row = reinterpret_cast<const float4*>(g_mean + (size_t)ar * D);
    const float4* x4row    = reinterpret_cast<const float4*>(x + (size_t)ar * D);

    // chunk kt covers K [kt*KC, kt*KC+KC): kt<8 -> mean row, else x row
    auto load_chunk = [&](int kt, float4 v[2]) {
        const bool is_mean = (kt < 8);
        const float4* srow = is_mean ? mean4row : x4row;
        const int kb4 = (is_mean ? kt * KC : kt * KC - 128) >> 2;
        v[0] = srow[kb4 + akq * 2 + 0];
        v[1] = srow[kb4 + akq * 2 + 1];
    };
    auto store_chunk = [&](int buf, const float4 v[2]) {
        float* Ab = As + buf * (KC * 128);
        #pragma unroll
        for (int i = 0; i < 2; i++) {
            int kk = (akq * 2 + i) * 4;
            Ab[(kk + 0) * 128 + am] = v[i].x;
            Ab[(kk + 1) * 128 + am] = v[i].y;
            Ab[(kk + 2) * 128 + am] = v[i].z;
            Ab[(kk + 3) * 128 + am] = v[i].w;
        }
    };

    // Prologue: chunk 0 into buffer 0
    {
        float4 v[2];
        load_chunk(0, v);
        store_chunk(0, v);
    }

    #pragma unroll 1
    for (int kt = 0; kt < KTOT / KC; kt++) {       // 16 chunks
        __syncthreads();   // covers stores to buf (kt&1) and frees buf ((kt+1)&1)

        float4 vnext[2];
        if (kt < KTOT / KC - 1) load_chunk(kt + 1, vnext);

        const float* Ab = As + (kt & 1) * (KC * 128);
        const int k0 = kt * KC;

        #pragma unroll
        for (int kk = 0; kk < KC; kk++) {
            const float4 a0 = *reinterpret_cast<const float4*>(&Ab[kk * 128 + ty8]);
            const float4 a1 = *reinterpret_cast<const float4*>(&Ab[kk * 128 + ty8 + 4]);
            const float4 b0 = *reinterpret_cast<const float4*>(&Bs[(k0 + kk) * 128 + tx8]);
            const float4 b1 = *reinterpret_cast<const float4*>(&Bs[(k0 + kk) * 128 + tx8 + 4]);

            unsigned long long bp[4];
            { F2U u; u.f = make_float2(b0.x, b0.y); bp[0] = u.u; }
            { F2U u; u.f = make_float2(b0.z, b0.w); bp[1] = u.u; }
            { F2U u; u.f = make_float2(b1.x, b1.y); bp[2] = u.u; }
            { F2U u; u.f = make_float2(b1.z, b1.w); bp[3] = u.u; }

            float av[8] = {a0.x, a0.y, a0.z, a0.w, a1.x, a1.y, a1.z, a1.w};
            #pragma unroll
            for (int m = 0; m < 8; m++) {
                unsigned long long as_ = splat2(av[m]);
                #pragma unroll
                for (int j = 0; j < 4; j++)
                    fma2(acc[m][j], as_, bp[j]);
            }
        }

        if (kt < KTOT / KC - 1) store_chunk((kt + 1) & 1, vnext);
    }

    // Epilogue: out = x + relu(acc + bias)
    const float4 ba = *reinterpret_cast<const float4*>(&bs[tx8]);
    const float4 bb = *reinterpret_cast<const float4*>(&bs[tx8 + 4]);
    #pragma unroll
    for (int m = 0; m < 8; m++) {
        int r = row0 + ty8 + m;
        if (r < N_NODES) {
            const float4* xr = reinterpret_cast<const float4*>(x + (size_t)r * D + tx8);
            float4* outr = reinterpret_cast<float4*>(out + (size_t)r * D + tx8);
            float4 xa = xr[0], xb = xr[1];
            F2U u; float4 o;
            u.u = acc[m][0];
            o.x = xa.x + fmaxf(u.f.x + ba.x, 0.f);
            o.y = xa.y + fmaxf(u.f.y + ba.y, 0.f);
            u.u = acc[m][1];
            o.z = xa.z + fmaxf(u.f.x + ba.z, 0.f);
            o.w = xa.w + fmaxf(u.f.y + ba.w, 0.f);
            outr[0] = o;
            u.u = acc[m][2];
            o.x = xb.x + fmaxf(u.f.x + bb.x, 0.f);
            o.y = xb.y + fmaxf(u.f.y + bb.y, 0.f);
            u.u = acc[m][3];
            o.z = xb.z + fmaxf(u.f.x + bb.z, 0.f);
            o.w = xb.w + fmaxf(u.f.y + bb.w, 0.f);
            outr[1] = o;
        }
    }
}

// ---------------------------------------------------------------------------
extern "C" void kernel_launch(void* const* d_in, const int* in_sizes, int n_in,
                              void* d_out, int out_size)
{
    const float* x  = (const float*)d_in[0];
    const int*   ei = (const int*)d_in[1];      // [2, E]: src = ei[0:E], dst = ei[E:2E]
    const float* Wl = (const float*)d_in[2];
    const float* bl = (const float*)d_in[3];
    const float* Wr = (const float*)d_in[4];
    float* out = (float*)d_out;

    const int* src = ei;
    const int* dst = ei + N_EDGES;

    zero_cnt_kernel<<<(N_NODES + 255) / 256, 256>>>();
    hist_kernel<<<(N_EDGES + 255) / 256, 256>>>(dst);
    scan1_kernel<<<N_SCAN_BLOCKS, SCAN_BLK>>>();
    scan2_kernel<<<1, SCAN_BLK>>>();
    scan3_kernel<<<(N_NODES + 255) / 256, 256>>>();
    fill_kernel<<<(N_EDGES + 255) / 256, 256>>>(src, dst);

    {
        long long threads = (long long)N_NODES * 32;
        int blocks = (int)((threads + 255) / 256);
        gather_kernel<<<blocks, 256>>>(reinterpret_cast<const float4*>(x));
    }

    {
        const int smem_bytes = (KTOT * 128 + 2 * KC * 128 + 128) * sizeof(float);
        cudaFuncSetAttribute(gemm_kernel,
                             cudaFuncAttributeMaxDynamicSharedMemorySize,
                             smem_bytes);
        int grid = (N_NODES + BM - 1) / BM;
        gemm_kernel<<<grid, 256, smem_bytes>>>(x, Wl, bl, Wr, out);
    }
}

// round 7
// speedup vs baseline: 2.3147x; 1.3226x over previous
#include <cuda_runtime.h>
#include <cuda_bf16.h>
#include <cstdint>

#define N_NODES 50000
#define D 128
#define N_EDGES 625000
#define SCAN_BLK 256
#define N_SCAN_BLOCKS ((N_NODES + SCAN_BLK - 1) / SCAN_BLK)   // 196

// Scratch (no cudaMalloc allowed)
__device__ float g_mean[(size_t)N_NODES * D];   // 25.6 MB
__device__ int   g_cnt[N_NODES];
__device__ int   g_start[N_NODES];
__device__ int   g_pos[N_NODES];
__device__ int   g_bsum[N_SCAN_BLOCKS];
__device__ int   g_boff[N_SCAN_BLOCKS];
__device__ int   g_esrc[N_EDGES];
// Pre-swizzled bf16 weight images: [phase][32KB], phase 0 = W_l^T, 1 = W_r^T
// Layout: rows = n (0..127), cols = k (0..127), blocked-atom + XOR swizzle.
__device__ __align__(16) uint8_t g_img_hi[2][32768];
__device__ __align__(16) uint8_t g_img_lo[2][32768];

// ---------------------------------------------------------------------------
// helpers
// ---------------------------------------------------------------------------
__device__ __forceinline__ uint32_t smem_to_u32(const void* p) {
    uint32_t a;
    asm("{ .reg .u64 t; cvta.to.shared.u64 t, %1; cvt.u32.u64 %0, t; }"
        : "=r"(a) : "l"(p));
    return a;
}
#define SMEM_SWIZZLE_128B(o) ((o) ^ (((o) >> 3) & 0x70))

// blocked-atom byte offset for (row, col) bf16 in a 128x128 tile:
// atom = 8 rows x 64 cols (1024 B); atoms: (row>>3) + (col>>6)*16
__device__ __forceinline__ uint32_t tile_off(int row, int col) {
    return (uint32_t)((((row >> 3) + ((col >> 6) << 4)) << 10) +
                      ((row & 7) << 7) + ((col & 63) << 1));
}

__device__ __forceinline__ uint32_t packbf(__nv_bfloat16 a, __nv_bfloat16 b) {
    __nv_bfloat162 t;
    t.x = a; t.y = b;
    return *reinterpret_cast<uint32_t*>(&t);
}

__device__ __forceinline__ void ldsm_x4(uint32_t r[4], uint32_t addr) {
    asm volatile("ldmatrix.sync.aligned.m8n8.x4.shared.b16 {%0,%1,%2,%3}, [%4];"
                 : "=r"(r[0]), "=r"(r[1]), "=r"(r[2]), "=r"(r[3]) : "r"(addr));
}

__device__ __forceinline__ void mma16816(float c[4], const uint32_t a[4],
                                         const uint32_t b[2]) {
    asm volatile(
        "mma.sync.aligned.m16n8k16.row.col.f32.bf16.bf16.f32 "
        "{%0,%1,%2,%3}, {%4,%5,%6,%7}, {%8,%9}, {%0,%1,%2,%3};"
        : "+f"(c[0]), "+f"(c[1]), "+f"(c[2]), "+f"(c[3])
        : "r"(a[0]), "r"(a[1]), "r"(a[2]), "r"(a[3]), "r"(b[0]), "r"(b[1]));
}

// ---------------------------------------------------------------------------
// prep: split+transpose+swizzle weights into bf16 hi/lo global images.
//   image element (n, k) = W[k][n]
// ---------------------------------------------------------------------------
__global__ void __launch_bounds__(256) prep_kernel(const float* __restrict__ Wl,
                                                   const float* __restrict__ Wr)
{
    int gid = blockIdx.x * 256 + threadIdx.x;   // 0..16383
    int p   = gid >> 13;
    int rem = gid & 8191;
    int n   = rem >> 6;
    int k   = (rem & 63) * 2;
    const float* W = p ? Wr : Wl;
    float v0 = W[(size_t)k * 128 + n];
    float v1 = W[(size_t)(k + 1) * 128 + n];
    __nv_bfloat16 h0 = __float2bfloat16_rn(v0);
    __nv_bfloat16 h1 = __float2bfloat16_rn(v1);
    __nv_bfloat16 l0 = __float2bfloat16_rn(v0 - __bfloat162float(h0));
    __nv_bfloat16 l1 = __float2bfloat16_rn(v1 - __bfloat162float(h1));
    uint32_t off = SMEM_SWIZZLE_128B(tile_off(n, k));
    *reinterpret_cast<uint32_t*>(&g_img_hi[p][off]) = packbf(h0, h1);
    *reinterpret_cast<uint32_t*>(&g_img_lo[p][off]) = packbf(l0, l1);
}

// ---------------------------------------------------------------------------
// CSR build + gather (round-5 measured-good, unchanged)
// ---------------------------------------------------------------------------
__global__ void zero_cnt_kernel() {
    int i = blockIdx.x * blockDim.x + threadIdx.x;
    if (i < N_NODES) g_cnt[i] = 0;
}

__global__ void hist_kernel(const int* __restrict__ dst) {
    int i = blockIdx.x * blockDim.x + threadIdx.x;
    if (i < N_EDGES) atomicAdd(&g_cnt[dst[i]], 1);
}

__global__ void scan1_kernel() {
    __shared__ int sh[SCAN_BLK];
    int t = threadIdx.x;
    int i = blockIdx.x * SCAN_BLK + t;
    int v = (i < N_NODES) ? g_cnt[i] : 0;
    sh[t] = v;
    __syncthreads();
    #pragma unroll
    for (int off = 1; off < SCAN_BLK; off <<= 1) {
        int t2 = (t >= off) ? sh[t - off] : 0;
        __syncthreads();
        sh[t] += t2;
        __syncthreads();
    }
    if (i < N_NODES) g_start[i] = sh[t] - v;
    if (t == SCAN_BLK - 1) g_bsum[blockIdx.x] = sh[t];
}

__global__ void scan2_kernel() {
    __shared__ int sh[SCAN_BLK];
    int t = threadIdx.x;
    int v = (t < N_SCAN_BLOCKS) ? g_bsum[t] : 0;
    sh[t] = v;
    __syncthreads();
    #pragma unroll
    for (int off = 1; off < SCAN_BLK; off <<= 1) {
        int t2 = (t >= off) ? sh[t - off] : 0;
        __syncthreads();
        sh[t] += t2;
        __syncthreads();
    }
    if (t < N_SCAN_BLOCKS) g_boff[t] = sh[t] - v;
}

__global__ void scan3_kernel() {
    int i = blockIdx.x * blockDim.x + threadIdx.x;
    if (i < N_NODES) {
        int s = g_start[i] + g_boff[i >> 8];
        g_start[i] = s;
        g_pos[i] = s;
    }
}

__global__ void fill_kernel(const int* __restrict__ src,
                            const int* __restrict__ dst) {
    int i = blockIdx.x * blockDim.x + threadIdx.x;
    if (i < N_EDGES) {
        int slot = atomicAdd(&g_pos[dst[i]], 1);
        g_esrc[slot] = src[i];
    }
}

__global__ void __launch_bounds__(256) gather_kernel(const float4* __restrict__ x4)
{
    int node = (blockIdx.x * blockDim.x + threadIdx.x) >> 5;
    int lane = threadIdx.x & 31;
    if (node >= N_NODES) return;

    int start = g_start[node];
    int deg   = g_cnt[node];
    int end   = start + deg;

    float4 acc = make_float4(0.f, 0.f, 0.f, 0.f);
    int e = start;
    for (; e + 4 <= end; e += 4) {
        int i0 = __ldg(&g_esrc[e]);
        int i1 = __ldg(&g_esrc[e + 1]);
        int i2 = __ldg(&g_esrc[e + 2]);
        int i3 = __ldg(&g_esrc[e + 3]);
        float4 v0 = x4[(size_t)i0 * (D / 4) + lane];
        float4 v1 = x4[(size_t)i1 * (D / 4) + lane];
        float4 v2 = x4[(size_t)i2 * (D / 4) + lane];
        float4 v3 = x4[(size_t)i3 * (D / 4) + lane];
        acc.x += (v0.x + v1.x) + (v2.x + v3.x);
        acc.y += (v0.y + v1.y) + (v2.y + v3.y);
        acc.z += (v0.z + v1.z) + (v2.z + v3.z);
        acc.w += (v0.w + v1.w) + (v2.w + v3.w);
    }
    for (; e < end; e++) {
        int i0 = __ldg(&g_esrc[e]);
        float4 v0 = x4[(size_t)i0 * (D / 4) + lane];
        acc.x += v0.x; acc.y += v0.y; acc.z += v0.z; acc.w += v0.w;
    }

    float rdeg = 1.0f / fmaxf((float)deg, 1.0f);
    acc.x *= rdeg; acc.y *= rdeg; acc.z *= rdeg; acc.w *= rdeg;
    reinterpret_cast<float4*>(g_mean)[(size_t)node * (D / 4) + lane] = acc;
}

// ---------------------------------------------------------------------------
// HMMA GEMM:  out = x + relu( g_mean @ W_l + x @ W_r + b )
//   128x128 block tile, 8 warps (warp tile 32x64), 2 phases of K=128,
//   bf16 split: hi*hi + hi*lo + lo*hi, fp32 accum in registers.
// ---------------------------------------------------------------------------
#define OFF_BIAS  0
#define OFF_AHI   1024
#define OFF_ALO   (OFF_AHI + 32768)
#define OFF_BHI   (OFF_ALO + 32768)
#define OFF_BLO   (OFF_BHI + 32768)
#define SMEM_TOTAL (OFF_BLO + 32768)

__global__ void __launch_bounds__(256, 1) gemm_mma_kernel(
    const float* __restrict__ x,
    const float* __restrict__ bias,
    float* __restrict__ out)
{
    extern __shared__ __align__(1024) char smem[];
    const uint32_t smem_base = smem_to_u32(smem);
    const int tid  = threadIdx.x;
    const int wid  = tid >> 5;
    const int lane = tid & 31;
    const int row0 = blockIdx.x * 128;

    // warp tile position: 4 warps along M, 2 along N
    const int wm = (wid & 3) * 32;
    const int wn = (wid >> 2) * 64;

    if (tid < 128) reinterpret_cast<float*>(smem + OFF_BIAS)[tid] = bias[tid];

    // A conversion assignment: row = tid&127, k-half = tid>>7
    const int am = tid & 127;
    const int kh = tid >> 7;             // 0 or 1 -> k base 0 / 64
    int ar = row0 + am;
    if (ar >= N_NODES) ar = N_NODES - 1;
    const float4* mean4 = reinterpret_cast<const float4*>(g_mean + (size_t)ar * D);
    const float4* x4r   = reinterpret_cast<const float4*>(x + (size_t)ar * D);

    // per-lane ldmatrix address components
    const int a_r  = ((lane >> 3) & 1) * 8 + (lane & 7);   // row within m16 tile
    const int a_c  = ((lane >> 4) & 1) * 8;                // col offset (k)
    const int b_r  = ((lane >> 4) & 1) * 8 + (lane & 7);   // row within n16 block
    const int b_c  = ((lane >> 3) & 1) * 8;                // col offset (k)

    float acc[2][8][4];
    #pragma unroll
    for (int mt = 0; mt < 2; mt++)
        #pragma unroll
        for (int nt = 0; nt < 8; nt++)
            #pragma unroll
            for (int j = 0; j < 4; j++)
                acc[mt][nt][j] = 0.f;

    #pragma unroll 1
    for (int phase = 0; phase < 2; phase++) {
        __syncthreads();   // free smem from previous phase / bias store

        // ---- copy B images for this phase (32 KB hi + 32 KB lo)
        {
            const uint4* shi = reinterpret_cast<const uint4*>(g_img_hi[phase]);
            const uint4* slo = reinterpret_cast<const uint4*>(g_img_lo[phase]);
            uint4* dhi = reinterpret_cast<uint4*>(smem + OFF_BHI);
            uint4* dlo = reinterpret_cast<uint4*>(smem + OFF_BLO);
            #pragma unroll
            for (int i = 0; i < 8; i++) {
                dhi[tid + 256 * i] = shi[tid + 256 * i];
                dlo[tid + 256 * i] = slo[tid + 256 * i];
            }
        }
        // ---- convert A half-row: 64 fp32 -> hi/lo bf16, swizzled stores
        {
            const float4* srow = phase ? x4r : mean4;
            #pragma unroll
            for (int g = 0; g < 8; g++) {
                int kbase = kh * 64 + g * 8;
                float4 v0 = srow[kbase / 4];
                float4 v1 = srow[kbase / 4 + 1];
                float vv[8] = {v0.x, v0.y, v0.z, v0.w, v1.x, v1.y, v1.z, v1.w};
                uint32_t hp[4], lp[4];
                #pragma unroll
                for (int j = 0; j < 4; j++) {
                    __nv_bfloat16 h0 = __float2bfloat16_rn(vv[2 * j]);
                    __nv_bfloat16 h1 = __float2bfloat16_rn(vv[2 * j + 1]);
                    __nv_bfloat16 l0 = __float2bfloat16_rn(vv[2 * j] - __bfloat162float(h0));
                    __nv_bfloat16 l1 = __float2bfloat16_rn(vv[2 * j + 1] - __bfloat162float(h1));
                    hp[j] = packbf(h0, h1);
                    lp[j] = packbf(l0, l1);
                }
                uint32_t off = SMEM_SWIZZLE_128B(tile_off(am, kbase));
                *reinterpret_cast<uint4*>(smem + OFF_AHI + off) =
                    make_uint4(hp[0], hp[1], hp[2], hp[3]);
                *reinterpret_cast<uint4*>(smem + OFF_ALO + off) =
                    make_uint4(lp[0], lp[1], lp[2], lp[3]);
            }
        }
        __syncthreads();

        // ---- 8 k-steps of 16, 3 split products each
        #pragma unroll 1
        for (int ks = 0; ks < 8; ks++) {
            const int kb = ks * 16;
            uint32_t ah[2][4], al[2][4], bh[4][4], bl[4][4];
            #pragma unroll
            for (int mt = 0; mt < 2; mt++) {
                uint32_t o = SMEM_SWIZZLE_128B(tile_off(wm + mt * 16 + a_r, kb + a_c));
                ldsm_x4(ah[mt], smem_base + OFF_AHI + o);
                ldsm_x4(al[mt], smem_base + OFF_ALO + o);
            }
            #pragma unroll
            for (int j = 0; j < 4; j++) {
                uint32_t o = SMEM_SWIZZLE_128B(tile_off(wn + j * 16 + b_r, kb + b_c));
                ldsm_x4(bh[j], smem_base + OFF_BHI + o);
                ldsm_x4(bl[j], smem_base + OFF_BLO + o);
            }
            #pragma unroll
            for (int mt = 0; mt < 2; mt++)
                #pragma unroll
                for (int j = 0; j < 4; j++) {
                    mma16816(acc[mt][2 * j],     ah[mt], &bh[j][0]);
                    mma16816(acc[mt][2 * j + 1], ah[mt], &bh[j][2]);
                    mma16816(acc[mt][2 * j],     ah[mt], &bl[j][0]);
                    mma16816(acc[mt][2 * j + 1], ah[mt], &bl[j][2]);
                    mma16816(acc[mt][2 * j],     al[mt], &bh[j][0]);
                    mma16816(acc[mt][2 * j + 1], al[mt], &bh[j][2]);
                }
        }
    }

    // ---- epilogue: out = x + relu(acc + bias)
    const float* bsp = reinterpret_cast<const float*>(smem + OFF_BIAS);
    #pragma unroll
    for (int mt = 0; mt < 2; mt++) {
        #pragma unroll
        for (int nt = 0; nt < 8; nt++) {
            int c  = wn + nt * 8 + (lane & 3) * 2;
            float2 bv = *reinterpret_cast<const float2*>(bsp + c);
            int r0 = row0 + wm + mt * 16 + (lane >> 2);
            int r1 = r0 + 8;
            if (r0 < N_NODES) {
                const float2 xv = *reinterpret_cast<const float2*>(x + (size_t)r0 * D + c);
                float2 o;
                o.x = xv.x + fmaxf(acc[mt][nt][0] + bv.x, 0.f);
                o.y = xv.y + fmaxf(acc[mt][nt][1] + bv.y, 0.f);
                *reinterpret_cast<float2*>(out + (size_t)r0 * D + c) = o;
            }
            if (r1 < N_NODES) {
                const float2 xv = *reinterpret_cast<const float2*>(x + (size_t)r1 * D + c);
                float2 o;
                o.x = xv.x + fmaxf(acc[mt][nt][2] + bv.x, 0.f);
                o.y = xv.y + fmaxf(acc[mt][nt][3] + bv.y, 0.f);
                *reinterpret_cast<float2*>(out + (size_t)r1 * D + c) = o;
            }
        }
    }
}

// ---------------------------------------------------------------------------
extern "C" void kernel_launch(void* const* d_in, const int* in_sizes, int n_in,
                              void* d_out, int out_size)
{
    const float* x  = (const float*)d_in[0];
    const int*   ei = (const int*)d_in[1];      // [2, E]
    const float* Wl = (const float*)d_in[2];
    const float* bl = (const float*)d_in[3];
    const float* Wr = (const float*)d_in[4];
    float* out = (float*)d_out;

    const int* src = ei;
    const int* dst = ei + N_EDGES;

    prep_kernel<<<64, 256>>>(Wl, Wr);
    zero_cnt_kernel<<<(N_NODES + 255) / 256, 256>>>();
    hist_kernel<<<(N_EDGES + 255) / 256, 256>>>(dst);
    scan1_kernel<<<N_SCAN_BLOCKS, SCAN_BLK>>>();
    scan2_kernel<<<1, SCAN_BLK>>>();
    scan3_kernel<<<(N_NODES + 255) / 256, 256>>>();
    fill_kernel<<<(N_EDGES + 255) / 256, 256>>>(src, dst);

    {
        long long threads = (long long)N_NODES * 32;
        int blocks = (int)((threads + 255) / 256);
        gather_kernel<<<blocks, 256>>>(reinterpret_cast<const float4*>(x));
    }

    {
        cudaFuncSetAttribute(gemm_mma_kernel,
                             cudaFuncAttributeMaxDynamicSharedMemorySize,
                             SMEM_TOTAL);
        int grid = (N_NODES + 127) / 128;   // 391
        gemm_mma_kernel<<<grid, 256, SMEM_TOTAL>>>(x, bl, out);
    }
}

// round 8
// speedup vs baseline: 2.3205x; 1.0025x over previous
#include <cuda_runtime.h>
#include <cuda_bf16.h>
#include <cstdint>

#define N_NODES 50000
#define D 128
#define N_EDGES 625000
#define SCAN_BLK 256
#define N_SCAN_BLOCKS ((N_NODES + SCAN_BLK - 1) / SCAN_BLK)   // 196

// Scratch (no cudaMalloc allowed)
__device__ float g_mean[(size_t)N_NODES * D];   // 25.6 MB
__device__ int   g_cnt[N_NODES];
__device__ int   g_start[N_NODES];              // block-local exclusive prefix
__device__ int   g_pos[N_NODES];                // fill cursor (zeroed)
__device__ int   g_bsum[N_SCAN_BLOCKS];
__device__ int   g_boff[N_SCAN_BLOCKS];
__device__ int   g_esrc[N_EDGES];
// Pre-swizzled bf16 weight images: [phase][32KB], phase 0 = W_l^T, 1 = W_r^T
__device__ __align__(16) uint8_t g_img_hi[2][32768];
__device__ __align__(16) uint8_t g_img_lo[2][32768];

// ---------------------------------------------------------------------------
// helpers
// ---------------------------------------------------------------------------
__device__ __forceinline__ uint32_t smem_to_u32(const void* p) {
    uint32_t a;
    asm("{ .reg .u64 t; cvta.to.shared.u64 t, %1; cvt.u32.u64 %0, t; }"
        : "=r"(a) : "l"(p));
    return a;
}
#define SMEM_SWIZZLE_128B(o) ((o) ^ (((o) >> 3) & 0x70))

// blocked-atom byte offset for (row, col) bf16 in a 128x128 tile
__device__ __forceinline__ uint32_t tile_off(int row, int col) {
    return (uint32_t)((((row >> 3) + ((col >> 6) << 4)) << 10) +
                      ((row & 7) << 7) + ((col & 63) << 1));
}

__device__ __forceinline__ uint32_t packbf(__nv_bfloat16 a, __nv_bfloat16 b) {
    __nv_bfloat162 t;
    t.x = a; t.y = b;
    return *reinterpret_cast<uint32_t*>(&t);
}

__device__ __forceinline__ void ldsm_x4(uint32_t r[4], uint32_t addr) {
    asm volatile("ldmatrix.sync.aligned.m8n8.x4.shared.b16 {%0,%1,%2,%3}, [%4];"
                 : "=r"(r[0]), "=r"(r[1]), "=r"(r[2]), "=r"(r[3]) : "r"(addr));
}

__device__ __forceinline__ void mma16816(float c[4], const uint32_t a[4],
                                         const uint32_t b[2]) {
    asm volatile(
        "mma.sync.aligned.m16n8k16.row.col.f32.bf16.bf16.f32 "
        "{%0,%1,%2,%3}, {%4,%5,%6,%7}, {%8,%9}, {%0,%1,%2,%3};"
        : "+f"(c[0]), "+f"(c[1]), "+f"(c[2]), "+f"(c[3])
        : "r"(a[0]), "r"(a[1]), "r"(a[2]), "r"(a[3]), "r"(b[0]), "r"(b[1]));
}

// ---------------------------------------------------------------------------
// 0) fused: zero g_cnt/g_pos + weight prep (split/transpose/swizzle)
// ---------------------------------------------------------------------------
__global__ void __launch_bounds__(256) prep_zero_kernel(const float* __restrict__ Wl,
                                                        const float* __restrict__ Wr)
{
    int gid = blockIdx.x * 256 + threadIdx.x;
    if (gid < N_NODES) {
        g_cnt[gid] = 0;
        g_pos[gid] = 0;
    }
    if (gid < 16384) {
        int p   = gid >> 13;
        int rem = gid & 8191;
        int n   = rem >> 6;
        int k   = (rem & 63) * 2;
        const float* W = p ? Wr : Wl;
        float v0 = W[(size_t)k * 128 + n];
        float v1 = W[(size_t)(k + 1) * 128 + n];
        __nv_bfloat16 h0 = __float2bfloat16_rn(v0);
        __nv_bfloat16 h1 = __float2bfloat16_rn(v1);
        __nv_bfloat16 l0 = __float2bfloat16_rn(v0 - __bfloat162float(h0));
        __nv_bfloat16 l1 = __float2bfloat16_rn(v1 - __bfloat162float(h1));
        uint32_t off = SMEM_SWIZZLE_128B(tile_off(n, k));
        *reinterpret_cast<uint32_t*>(&g_img_hi[p][off]) = packbf(h0, h1);
        *reinterpret_cast<uint32_t*>(&g_img_lo[p][off]) = packbf(l0, l1);
    }
}

// ---------------------------------------------------------------------------
// 1) histogram of dst, 4 edges per thread (int4)
// ---------------------------------------------------------------------------
__global__ void __launch_bounds__(256) hist_kernel(const int* __restrict__ dst) {
    int i = (blockIdx.x * 256 + threadIdx.x) * 4;
    if (i < N_EDGES) {
        int4 d = *reinterpret_cast<const int4*>(dst + i);
        atomicAdd(&g_cnt[d.x], 1);
        atomicAdd(&g_cnt[d.y], 1);
        atomicAdd(&g_cnt[d.z], 1);
        atomicAdd(&g_cnt[d.w], 1);
    }
}

// ---------------------------------------------------------------------------
// 2a) per-block exclusive scan of g_cnt; block sums -> g_bsum
// ---------------------------------------------------------------------------
__global__ void scan1_kernel() {
    __shared__ int sh[SCAN_BLK];
    int t = threadIdx.x;
    int i = blockIdx.x * SCAN_BLK + t;
    int v = (i < N_NODES) ? g_cnt[i] : 0;
    sh[t] = v;
    __syncthreads();
    #pragma unroll
    for (int off = 1; off < SCAN_BLK; off <<= 1) {
        int t2 = (t >= off) ? sh[t - off] : 0;
        __syncthreads();
        sh[t] += t2;
        __syncthreads();
    }
    if (i < N_NODES) g_start[i] = sh[t] - v;
    if (t == SCAN_BLK - 1) g_bsum[blockIdx.x] = sh[t];
}

// ---------------------------------------------------------------------------
// 2b) exclusive scan of the 196 block sums
// ---------------------------------------------------------------------------
__global__ void scan2_kernel() {
    __shared__ int sh[SCAN_BLK];
    int t = threadIdx.x;
    int v = (t < N_SCAN_BLOCKS) ? g_bsum[t] : 0;
    sh[t] = v;
    __syncthreads();
    #pragma unroll
    for (int off = 1; off < SCAN_BLK; off <<= 1) {
        int t2 = (t >= off) ? sh[t - off] : 0;
        __syncthreads();
        sh[t] += t2;
        __syncthreads();
    }
    if (t < N_SCAN_BLOCKS) g_boff[t] = sh[t] - v;
}

// ---------------------------------------------------------------------------
// 3) fill dst-sorted edge list, 4 edges per thread; CSR start folded in here
// ---------------------------------------------------------------------------
__global__ void __launch_bounds__(256) fill_kernel(const int* __restrict__ src,
                                                   const int* __restrict__ dst) {
    int i = (blockIdx.x * 256 + threadIdx.x) * 4;
    if (i < N_EDGES) {
        int4 s = *reinterpret_cast<const int4*>(src + i);
        int4 d = *reinterpret_cast<const int4*>(dst + i);
        {
            int base = g_start[d.x] + g_boff[d.x >> 8];
            g_esrc[base + atomicAdd(&g_pos[d.x], 1)] = s.x;
        }
        {
            int base = g_start[d.y] + g_boff[d.y >> 8];
            g_esrc[base + atomicAdd(&g_pos[d.y], 1)] = s.y;
        }
        {
            int base = g_start[d.z] + g_boff[d.z >> 8];
            g_esrc[base + atomicAdd(&g_pos[d.z], 1)] = s.z;
        }
        {
            int base = g_start[d.w] + g_boff[d.w >> 8];
            g_esrc[base + atomicAdd(&g_pos[d.w], 1)] = s.w;
        }
    }
}

// ---------------------------------------------------------------------------
// 4) pull-aggregate: one warp per node, lane = one float4 column, MLP=8.
// ---------------------------------------------------------------------------
__global__ void __launch_bounds__(256) gather_kernel(const float4* __restrict__ x4)
{
    int node = (blockIdx.x * blockDim.x + threadIdx.x) >> 5;
    int lane = threadIdx.x & 31;
    if (node >= N_NODES) return;

    int start = g_start[node] + g_boff[node >> 8];
    int deg   = g_cnt[node];
    int end   = start + deg;

    float4 acc = make_float4(0.f, 0.f, 0.f, 0.f);
    int e = start;
    for (; e + 8 <= end; e += 8) {
        int idx[8];
        #pragma unroll
        for (int j = 0; j < 8; j++) idx[j] = __ldg(&g_esrc[e + j]);
        float4 v[8];
        #pragma unroll
        for (int j = 0; j < 8; j++) v[j] = x4[(size_t)idx[j] * (D / 4) + lane];
        float4 s0, s1;
        s0.x = (v[0].x + v[1].x) + (v[2].x + v[3].x);
        s0.y = (v[0].y + v[1].y) + (v[2].y + v[3].y);
        s0.z = (v[0].z + v[1].z) + (v[2].z + v[3].z);
        s0.w = (v[0].w + v[1].w) + (v[2].w + v[3].w);
        s1.x = (v[4].x + v[5].x) + (v[6].x + v[7].x);
        s1.y = (v[4].y + v[5].y) + (v[6].y + v[7].y);
        s1.z = (v[4].z + v[5].z) + (v[6].z + v[7].z);
        s1.w = (v[4].w + v[5].w) + (v[6].w + v[7].w);
        acc.x += s0.x + s1.x;
        acc.y += s0.y + s1.y;
        acc.z += s0.z + s1.z;
        acc.w += s0.w + s1.w;
    }
    for (; e + 4 <= end; e += 4) {
        int i0 = __ldg(&g_esrc[e]);
        int i1 = __ldg(&g_esrc[e + 1]);
        int i2 = __ldg(&g_esrc[e + 2]);
        int i3 = __ldg(&g_esrc[e + 3]);
        float4 v0 = x4[(size_t)i0 * (D / 4) + lane];
        float4 v1 = x4[(size_t)i1 * (D / 4) + lane];
        float4 v2 = x4[(size_t)i2 * (D / 4) + lane];
        float4 v3 = x4[(size_t)i3 * (D / 4) + lane];
        acc.x += (v0.x + v1.x) + (v2.x + v3.x);
        acc.y += (v0.y + v1.y) + (v2.y + v3.y);
        acc.z += (v0.z + v1.z) + (v2.z + v3.z);
        acc.w += (v0.w + v1.w) + (v2.w + v3.w);
    }
    for (; e < end; e++) {
        int i0 = __ldg(&g_esrc[e]);
        float4 v0 = x4[(size_t)i0 * (D / 4) + lane];
        acc.x += v0.x; acc.y += v0.y; acc.z += v0.z; acc.w += v0.w;
    }

    float rdeg = 1.0f / fmaxf((float)deg, 1.0f);
    acc.x *= rdeg; acc.y *= rdeg; acc.z *= rdeg; acc.w *= rdeg;
    reinterpret_cast<float4*>(g_mean)[(size_t)node * (D / 4) + lane] = acc;
}

// ---------------------------------------------------------------------------
// 5) HMMA GEMM (round-7 measured good, unchanged):
//    out = x + relu( g_mean @ W_l + x @ W_r + b )
// ---------------------------------------------------------------------------
#define OFF_BIAS  0
#define OFF_AHI   1024
#define OFF_ALO   (OFF_AHI + 32768)
#define OFF_BHI   (OFF_ALO + 32768)
#define OFF_BLO   (OFF_BHI + 32768)
#define SMEM_TOTAL (OFF_BLO + 32768)

__global__ void __launch_bounds__(256, 1) gemm_mma_kernel(
    const float* __restrict__ x,
    const float* __restrict__ bias,
    float* __restrict__ out)
{
    extern __shared__ __align__(1024) char smem[];
    const uint32_t smem_base = smem_to_u32(smem);
    const int tid  = threadIdx.x;
    const int wid  = tid >> 5;
    const int lane = tid & 31;
    const int row0 = blockIdx.x * 128;

    const int wm = (wid & 3) * 32;
    const int wn = (wid >> 2) * 64;

    if (tid < 128) reinterpret_cast<float*>(smem + OFF_BIAS)[tid] = bias[tid];

    const int am = tid & 127;
    const int kh = tid >> 7;
    int ar = row0 + am;
    if (ar >= N_NODES) ar = N_NODES - 1;
    const float4* mean4 = reinterpret_cast<const float4*>(g_mean + (size_t)ar * D);
    const float4* x4r   = reinterpret_cast<const float4*>(x + (size_t)ar * D);

    const int a_r  = ((lane >> 3) & 1) * 8 + (lane & 7);
    const int a_c  = ((lane >> 4) & 1) * 8;
    const int b_r  = ((lane >> 4) & 1) * 8 + (lane & 7);
    const int b_c  = ((lane >> 3) & 1) * 8;

    float acc[2][8][4];
    #pragma unroll
    for (int mt = 0; mt < 2; mt++)
        #pragma unroll
        for (int nt = 0; nt < 8; nt++)
            #pragma unroll
            for (int j = 0; j < 4; j++)
                acc[mt][nt][j] = 0.f;

    #pragma unroll 1
    for (int phase = 0; phase < 2; phase++) {
        __syncthreads();

        {
            const uint4* shi = reinterpret_cast<const uint4*>(g_img_hi[phase]);
            const uint4* slo = reinterpret_cast<const uint4*>(g_img_lo[phase]);
            uint4* dhi = reinterpret_cast<uint4*>(smem + OFF_BHI);
            uint4* dlo = reinterpret_cast<uint4*>(smem + OFF_BLO);
            #pragma unroll
            for (int i = 0; i < 8; i++) {
                dhi[tid + 256 * i] = shi[tid + 256 * i];
                dlo[tid + 256 * i] = slo[tid + 256 * i];
            }
        }
        {
            const float4* srow = phase ? x4r : mean4;
            #pragma unroll
            for (int g = 0; g < 8; g++) {
                int kbase = kh * 64 + g * 8;
                float4 v0 = srow[kbase / 4];
                float4 v1 = srow[kbase / 4 + 1];
                float vv[8] = {v0.x, v0.y, v0.z, v0.w, v1.x, v1.y, v1.z, v1.w};
                uint32_t hp[4], lp[4];
                #pragma unroll
                for (int j = 0; j < 4; j++) {
                    __nv_bfloat16 h0 = __float2bfloat16_rn(vv[2 * j]);
                    __nv_bfloat16 h1 = __float2bfloat16_rn(vv[2 * j + 1]);
                    __nv_bfloat16 l0 = __float2bfloat16_rn(vv[2 * j] - __bfloat162float(h0));
                    __nv_bfloat16 l1 = __float2bfloat16_rn(vv[2 * j + 1] - __bfloat162float(h1));
                    hp[j] = packbf(h0, h1);
                    lp[j] = packbf(l0, l1);
                }
                uint32_t off = SMEM_SWIZZLE_128B(tile_off(am, kbase));
                *reinterpret_cast<uint4*>(smem + OFF_AHI + off) =
                    make_uint4(hp[0], hp[1], hp[2], hp[3]);
                *reinterpret_cast<uint4*>(smem + OFF_ALO + off) =
                    make_uint4(lp[0], lp[1], lp[2], lp[3]);
            }
        }
        __syncthreads();

        #pragma unroll 1
        for (int ks = 0; ks < 8; ks++) {
            const int kb = ks * 16;
            uint32_t ah[2][4], al[2][4], bh[4][4], bl[4][4];
            #pragma unroll
            for (int mt = 0; mt < 2; mt++) {
                uint32_t o = SMEM_SWIZZLE_128B(tile_off(wm + mt * 16 + a_r, kb + a_c));
                ldsm_x4(ah[mt], smem_base + OFF_AHI + o);
                ldsm_x4(al[mt], smem_base + OFF_ALO + o);
            }
            #pragma unroll
            for (int j = 0; j < 4; j++) {
                uint32_t o = SMEM_SWIZZLE_128B(tile_off(wn + j * 16 + b_r, kb + b_c));
                ldsm_x4(bh[j], smem_base + OFF_BHI + o);
                ldsm_x4(bl[j], smem_base + OFF_BLO + o);
            }
            #pragma unroll
            for (int mt = 0; mt < 2; mt++)
                #pragma unroll
                for (int j = 0; j < 4; j++) {
                    mma16816(acc[mt][2 * j],     ah[mt], &bh[j][0]);
                    mma16816(acc[mt][2 * j + 1], ah[mt], &bh[j][2]);
                    mma16816(acc[mt][2 * j],     ah[mt], &bl[j][0]);
                    mma16816(acc[mt][2 * j + 1], ah[mt], &bl[j][2]);
                    mma16816(acc[mt][2 * j],     al[mt], &bh[j][0]);
                    mma16816(acc[mt][2 * j + 1], al[mt], &bh[j][2]);
                }
        }
    }

    const float* bsp = reinterpret_cast<const float*>(smem + OFF_BIAS);
    #pragma unroll
    for (int mt = 0; mt < 2; mt++) {
        #pragma unroll
        for (int nt = 0; nt < 8; nt++) {
            int c  = wn + nt * 8 + (lane & 3) * 2;
            float2 bv = *reinterpret_cast<const float2*>(bsp + c);
            int r0 = row0 + wm + mt * 16 + (lane >> 2);
            int r1 = r0 + 8;
            if (r0 < N_NODES) {
                const float2 xv = *reinterpret_cast<const float2*>(x + (size_t)r0 * D + c);
                float2 o;
                o.x = xv.x + fmaxf(acc[mt][nt][0] + bv.x, 0.f);
                o.y = xv.y + fmaxf(acc[mt][nt][1] + bv.y, 0.f);
                *reinterpret_cast<float2*>(out + (size_t)r0 * D + c) = o;
            }
            if (r1 < N_NODES) {
                const float2 xv = *reinterpret_cast<const float2*>(x + (size_t)r1 * D + c);
                float2 o;
                o.x = xv.x + fmaxf(acc[mt][nt][2] + bv.x, 0.f);
                o.y = xv.y + fmaxf(acc[mt][nt][3] + bv.y, 0.f);
                *reinterpret_cast<float2*>(out + (size_t)r1 * D + c) = o;
            }
        }
    }
}

// ---------------------------------------------------------------------------
extern "C" void kernel_launch(void* const* d_in, const int* in_sizes, int n_in,
                              void* d_out, int out_size)
{
    const float* x  = (const float*)d_in[0];
    const int*   ei = (const int*)d_in[1];      // [2, E]
    const float* Wl = (const float*)d_in[2];
    const float* bl = (const float*)d_in[3];
    const float* Wr = (const float*)d_in[4];
    float* out = (float*)d_out;

    const int* src = ei;
    const int* dst = ei + N_EDGES;

    prep_zero_kernel<<<(N_NODES + 255) / 256, 256>>>(Wl, Wr);          // 0
    hist_kernel<<<(N_EDGES / 4 + 255) / 256, 256>>>(dst);              // 1
    scan1_kernel<<<N_SCAN_BLOCKS, SCAN_BLK>>>();                       // 2
    scan2_kernel<<<1, SCAN_BLK>>>();                                   // 3
    fill_kernel<<<(N_EDGES / 4 + 255) / 256, 256>>>(src, dst);         // 4

    {
        long long threads = (long long)N_NODES * 32;
        int blocks = (int)((threads + 255) / 256);
        gather_kernel<<<blocks, 256>>>(reinterpret_cast<const float4*>(x));  // 5
    }

    {
        cudaFuncSetAttribute(gemm_mma_kernel,
                             cudaFuncAttributeMaxDynamicSharedMemorySize,
                             SMEM_TOTAL);
        int grid = (N_NODES + 127) / 128;   // 391
        gemm_mma_kernel<<<grid, 256, SMEM_TOTAL>>>(x, bl, out);        // 6
    }
}